// round 2
// baseline (speedup 1.0000x reference)
#include <cuda_runtime.h>

#define THREADS 512
#define ROWS    128
#define HID     256
#define H3      128
#define NG      3
#define KT      32
#define PB2     260   // Bs pitch for layer2 (256+4, keeps float4 alignment, spreads banks)
#define PB3     132   // Bs pitch for layer3 (128+4)
#define P2      256   // h2 pitch [m][n]
#define P3      132   // h3 pitch [m][k]

// smem float offsets
#define OFF_HBUF 0
#define SZ_HBUF  32768          // max(h1 256*128, h2 128*256, h3 128*132)
#define OFF_BS   (OFF_HBUF + SZ_HBUF)
#define SZ_BS    (KT * PB2)     // 8320, also covers layer3 tile (32*132=4224)
#define OFF_XS   (OFF_BS + SZ_BS)
#define SZ_XS    (ROWS * 8)
#define OFF_W1   (OFF_XS + SZ_XS)
#define SZ_W1    (HID * 8)
#define OFF_B1   (OFF_W1 + SZ_W1)
#define OFF_B2   (OFF_B1 + HID)
#define OFF_B3   (OFF_B2 + HID)
#define OFF_W4   (OFF_B3 + H3)
#define OFF_B4   (OFF_W4 + NG * H3)
#define SMEM_FLOATS (OFF_B4 + 4)

__device__ __forceinline__ float silu_f(float x) {
    return x * __frcp_rn(1.0f + __expf(-x));
}

extern "C" __global__ void __launch_bounds__(THREADS)
mdp_mlp_kernel(const float* __restrict__ log_p,
               const float* __restrict__ log_y,
               const float* __restrict__ log_xb,
               const float* __restrict__ log_q,
               const float* __restrict__ W1, const float* __restrict__ b1,
               const float* __restrict__ W2, const float* __restrict__ b2,
               const float* __restrict__ W3, const float* __restrict__ b3,
               const float* __restrict__ W4, const float* __restrict__ b4,
               const float* __restrict__ log_beta,
               const float* __restrict__ log_delta,
               float* __restrict__ out)
{
    extern __shared__ float smem[];
    float* hbuf = smem + OFF_HBUF;
    float* Bs   = smem + OFF_BS;
    float* xs   = smem + OFF_XS;
    float* W1s  = smem + OFF_W1;
    float* b1s  = smem + OFF_B1;
    float* b2s  = smem + OFF_B2;
    float* b3s  = smem + OFF_B3;
    float* W4s  = smem + OFF_W4;
    float* b4s  = smem + OFF_B4;

    const int tid  = threadIdx.x;
    const int row0 = blockIdx.x * ROWS;
    const int warp = tid >> 5;
    const int lane = tid & 31;

    // scalars (L2/const-cached, negligible)
    const float delta = __frcp_rn(1.0f + __expf(-log_delta[0]));
    float beta = __expf(log_beta[0]);
    beta = fminf(fmaxf(beta, 0.5f), 20.0f);

    // ---- stage inputs + weights ----
    if (tid < ROWS) {
        const int m = tid, r = row0 + m;
        xs[m*8+0] = log_p[r*3+0];
        xs[m*8+1] = log_p[r*3+1];
        xs[m*8+2] = log_p[r*3+2];
        xs[m*8+3] = log_y[r];
        #pragma unroll
        for (int g = 0; g < 3; g++)
            xs[m*8+4+g] = delta * log_xb[r*3+g] + (1.0f - delta) * log_q[r*3+g];
        xs[m*8+7] = 0.0f;
    }
    for (int idx = tid; idx < HID*8; idx += THREADS) {
        const int k = idx >> 3, i = idx & 7;
        W1s[idx] = (i < 7) ? W1[k*7 + i] : 0.0f;
    }
    for (int idx = tid; idx < HID; idx += THREADS) { b1s[idx] = b1[idx]; b2s[idx] = b2[idx]; }
    if (tid < H3)      b3s[tid] = b3[tid];
    if (tid < NG*H3)   W4s[tid] = W4[tid];
    if (tid < NG)      b4s[tid] = b4[tid];
    __syncthreads();

    // ---- layer 1: h1[k][m] (pitch 128), silu(x @ W1^T + b1) ----
    {
        const int m = tid & 127;
        const int kbase = (tid >> 7) * 64;
        float xr[7];
        #pragma unroll
        for (int i = 0; i < 7; i++) xr[i] = xs[m*8 + i];
        #pragma unroll 4
        for (int j = 0; j < 64; j++) {
            const int k = kbase + j;
            float s = b1s[k];
            #pragma unroll
            for (int i = 0; i < 7; i++) s = fmaf(xr[i], W1s[k*8 + i], s);
            hbuf[k*128 + m] = silu_f(s);
        }
    }

    // ---- layer 2: [128 x 256] = h1[128,256] @ W2^T ; 8x8 per thread ----
    const int ty2 = tid >> 5;   // 0..15 : 8 rows each
    const int tx2 = tid & 31;   // 0..31 : 8 cols each
    float acc[8][8];
    #pragma unroll
    for (int i = 0; i < 8; i++)
        #pragma unroll
        for (int j = 0; j < 8; j++) acc[i][j] = 0.0f;

    for (int kt = 0; kt < HID; kt += KT) {
        __syncthreads();
        // stage Bs[kk][n] = W2[n][kt+kk]; warp handles 16 n rows, lane = kk
        #pragma unroll
        for (int r = 0; r < 16; r++) {
            const int n = warp*16 + r;
            Bs[lane*PB2 + n] = W2[n*HID + kt + lane];
        }
        __syncthreads();
        #pragma unroll
        for (int kk = 0; kk < KT; kk++) {
            const float4 a0 = *(const float4*)&hbuf[(kt+kk)*128 + ty2*8];
            const float4 a1 = *(const float4*)&hbuf[(kt+kk)*128 + ty2*8 + 4];
            const float4 c0 = *(const float4*)&Bs[kk*PB2 + tx2*8];
            const float4 c1 = *(const float4*)&Bs[kk*PB2 + tx2*8 + 4];
            const float a[8] = {a0.x,a0.y,a0.z,a0.w,a1.x,a1.y,a1.z,a1.w};
            const float b[8] = {c0.x,c0.y,c0.z,c0.w,c1.x,c1.y,c1.z,c1.w};
            #pragma unroll
            for (int i = 0; i < 8; i++)
                #pragma unroll
                for (int j = 0; j < 8; j++)
                    acc[i][j] = fmaf(a[i], b[j], acc[i][j]);
        }
    }
    __syncthreads();
    // epilogue: silu(acc + b2) -> h2[m][n] (pitch 256)
    {
        float bb[8];
        #pragma unroll
        for (int j = 0; j < 8; j++) bb[j] = b2s[tx2*8 + j];
        #pragma unroll
        for (int i = 0; i < 8; i++) {
            const int m = ty2*8 + i;
            float v[8];
            #pragma unroll
            for (int j = 0; j < 8; j++) v[j] = silu_f(acc[i][j] + bb[j]);
            *(float4*)&hbuf[m*P2 + tx2*8]     = make_float4(v[0], v[1], v[2], v[3]);
            *(float4*)&hbuf[m*P2 + tx2*8 + 4] = make_float4(v[4], v[5], v[6], v[7]);
        }
    }
    __syncthreads();

    // ---- layer 3: [128 x 128] = h2[128,256] @ W3^T ; 4x8 per thread ----
    const int r3 = tid >> 4;    // 0..31 : 4 rows each
    const int c3 = tid & 15;    // 0..15 : 8 cols each
    float acc3[4][8];
    #pragma unroll
    for (int i = 0; i < 4; i++)
        #pragma unroll
        for (int j = 0; j < 8; j++) acc3[i][j] = 0.0f;

    for (int kt = 0; kt < HID; kt += KT) {
        __syncthreads();
        // stage Bs[kk][n3] = W3[n3][kt+kk]; warp handles 8 n rows, lane = kk
        #pragma unroll
        for (int r = 0; r < 8; r++) {
            const int n = warp*8 + r;
            Bs[lane*PB3 + n] = W3[n*HID + kt + lane];
        }
        __syncthreads();
        #pragma unroll
        for (int kk = 0; kk < KT; kk++) {
            const int k = kt + kk;
            float a[4];
            #pragma unroll
            for (int i = 0; i < 4; i++) a[i] = hbuf[(r3*4 + i)*P2 + k];
            const float4 c0 = *(const float4*)&Bs[kk*PB3 + c3*8];
            const float4 c1 = *(const float4*)&Bs[kk*PB3 + c3*8 + 4];
            const float b[8] = {c0.x,c0.y,c0.z,c0.w,c1.x,c1.y,c1.z,c1.w};
            #pragma unroll
            for (int i = 0; i < 4; i++)
                #pragma unroll
                for (int j = 0; j < 8; j++)
                    acc3[i][j] = fmaf(a[i], b[j], acc3[i][j]);
        }
    }
    __syncthreads();
    // epilogue: silu(acc3 + b3) -> h3[m][k] (pitch 132)
    {
        float bb[8];
        #pragma unroll
        for (int j = 0; j < 8; j++) bb[j] = b3s[c3*8 + j];
        #pragma unroll
        for (int i = 0; i < 4; i++) {
            const int m = r3*4 + i;
            float v[8];
            #pragma unroll
            for (int j = 0; j < 8; j++) v[j] = silu_f(acc3[i][j] + bb[j]);
            *(float4*)&hbuf[m*P3 + c3*8]     = make_float4(v[0], v[1], v[2], v[3]);
            *(float4*)&hbuf[m*P3 + c3*8 + 4] = make_float4(v[4], v[5], v[6], v[7]);
        }
    }
    __syncthreads();

    // ---- layer 4 + softmax: one thread per row ----
    if (tid < ROWS) {
        const int m = tid;
        float l[NG];
        #pragma unroll
        for (int g = 0; g < NG; g++) {
            float s = b4s[g];
            #pragma unroll 8
            for (int k = 0; k < H3; k += 4) {
                const float4 hv = *(const float4*)&hbuf[m*P3 + k];
                const float4 wv = *(const float4*)&W4s[g*H3 + k];
                s = fmaf(hv.x, wv.x, s);
                s = fmaf(hv.y, wv.y, s);
                s = fmaf(hv.z, wv.z, s);
                s = fmaf(hv.w, wv.w, s);
            }
            l[g] = s * beta;
        }
        float mx = fmaxf(l[0], fmaxf(l[1], l[2]));
        float e0 = __expf(l[0] - mx);
        float e1 = __expf(l[1] - mx);
        float e2 = __expf(l[2] - mx);
        const float inv = __frcp_rn(e0 + e1 + e2);
        const int r = row0 + m;
        out[r*3 + 0] = e0 * inv;
        out[r*3 + 1] = e1 * inv;
        out[r*3 + 2] = e2 * inv;
    }
}

extern "C" void kernel_launch(void* const* d_in, const int* in_sizes, int n_in,
                              void* d_out, int out_size)
{
    const float* log_p     = (const float*)d_in[0];
    const float* log_y     = (const float*)d_in[1];
    const float* log_xb    = (const float*)d_in[2];
    const float* log_q     = (const float*)d_in[3];
    const float* W1        = (const float*)d_in[4];
    const float* b1        = (const float*)d_in[5];
    const float* W2        = (const float*)d_in[6];
    const float* b2        = (const float*)d_in[7];
    const float* W3        = (const float*)d_in[8];
    const float* b3        = (const float*)d_in[9];
    const float* W4        = (const float*)d_in[10];
    const float* b4        = (const float*)d_in[11];
    const float* log_beta  = (const float*)d_in[12];
    const float* log_delta = (const float*)d_in[13];
    float* out = (float*)d_out;

    const int B = in_sizes[1];           // log_y has B elements
    const int grid = B / ROWS;           // 262144 / 128 = 2048
    const size_t smem_bytes = (size_t)SMEM_FLOATS * sizeof(float);

    cudaFuncSetAttribute(mdp_mlp_kernel,
                         cudaFuncAttributeMaxDynamicSharedMemorySize,
                         (int)smem_bytes);

    mdp_mlp_kernel<<<grid, THREADS, smem_bytes>>>(
        log_p, log_y, log_xb, log_q,
        W1, b1, W2, b2, W3, b3, W4, b4,
        log_beta, log_delta, out);
}

// round 4
// speedup vs baseline: 2.2660x; 2.2660x over previous
#include <cuda_runtime.h>
#include <cuda_bf16.h>
#include <cstdint>

#define THREADS 512
#define ROWSPB  128
#define APITCH  264      // bf16 units per A row (528 bytes, 33 x 16B -> conflict-free ldmatrix)
#define BPITCHB 80       // bytes per weight row in a k32 chunk (64 data + 16 pad)

// ---- smem byte offsets (from 128-aligned base) ----
#define OFF_AH   0                 // 128 x 528 = 67584
#define OFF_AL   67584             // 67584
#define OFF_WB   135168            // 2 buffers x 40960
#define OFF_W1S  217088            // 8192
#define OFF_B1S  225280            // 1024
#define OFF_B2S  226304            // 1024
#define OFF_B3S  227328            // 512
#define OFF_W4S  227840            // 1536
#define OFF_B4S  229376            // 16
#define OFF_MB   229392            // 2 mbarriers
#define SMEM_BYTES (229408 + 128)

// global weight image: W2 = 8 chunks x (hi 20480 | lo 20480); W3 at 327680 = 8 x (hi 10240 | lo 10240)
#define IMG_W3_BASE 327680
__device__ __align__(16) unsigned char g_wimg[327680 + 163840];

// ---------------- helpers ----------------
__device__ __forceinline__ uint32_t smem_u32(const void* p) {
    uint32_t a;
    asm("{ .reg .u64 t; cvta.to.shared.u64 t, %1; cvt.u32.u64 %0, t; }" : "=r"(a) : "l"(p));
    return a;
}

#define MBARRIER_INIT(addr, cnt) \
    asm volatile("mbarrier.init.shared.b64 [%0], %1;" :: "r"((uint32_t)(addr)), "r"((uint32_t)(cnt)) : "memory")
#define MBARRIER_EXPECT_TX(addr, bytes) \
    asm volatile("mbarrier.arrive.expect_tx.shared.b64 _, [%0], %1;" :: "r"((uint32_t)(addr)), "r"((uint32_t)(bytes)) : "memory")
#define MBARRIER_WAIT_PARITY(addr, parity) do {                                   \
    uint32_t _mb = (uint32_t)(addr); uint32_t _p = (uint32_t)(parity);            \
    asm volatile(                                                                 \
        "{\n\t.reg .pred P;\n\t"                                                  \
        "WL_%=:\n\t"                                                              \
        "mbarrier.try_wait.parity.acquire.cta.shared::cta.b64 P, [%0], %1, 0x989680;\n\t" \
        "@P bra.uni WD_%=;\n\t"                                                   \
        "bra.uni WL_%=;\n\t"                                                      \
        "WD_%=:\n\t}"                                                             \
        :: "r"(_mb), "r"(_p) : "memory");                                         \
} while (0)
#define FENCE_PROXY_ASYNC() asm volatile("fence.proxy.async.shared::cta;" ::: "memory")

__device__ __forceinline__ void bulk_copy(uint32_t smem_dst, const void* gsrc,
                                          uint32_t bytes, uint32_t mbar) {
    uint64_t g = (uint64_t)__cvta_generic_to_global(gsrc);
    asm volatile(
        "cp.async.bulk.shared::cta.global.mbarrier::complete_tx::bytes [%0], [%1], %2, [%3];"
        :: "r"(smem_dst), "l"(g), "r"(bytes), "r"(mbar) : "memory");
}

__device__ __forceinline__ void ldsm4(uint32_t a, uint32_t* r) {
    asm volatile("ldmatrix.sync.aligned.m8n8.x4.shared.b16 {%0,%1,%2,%3}, [%4];"
        : "=r"(r[0]), "=r"(r[1]), "=r"(r[2]), "=r"(r[3]) : "r"(a));
}

__device__ __forceinline__ void mma16816(float* d, const uint32_t* a, uint32_t b0, uint32_t b1) {
    asm volatile("mma.sync.aligned.m16n8k16.row.col.f32.bf16.bf16.f32 "
        "{%0,%1,%2,%3}, {%4,%5,%6,%7}, {%8,%9}, {%0,%1,%2,%3};"
        : "+f"(d[0]), "+f"(d[1]), "+f"(d[2]), "+f"(d[3])
        : "r"(a[0]), "r"(a[1]), "r"(a[2]), "r"(a[3]), "r"(b0), "r"(b1));
}

__device__ __forceinline__ float silu_f(float x) {
    return __fdividef(x, 1.0f + __expf(-x));
}

__device__ __forceinline__ void bsplit2(float a, float b, uint32_t& hi, uint32_t& lo) {
    __nv_bfloat162 h = __floats2bfloat162_rn(a, b);
    __nv_bfloat162 l = __floats2bfloat162_rn(a - __low2float(h), b - __high2float(h));
    hi = *reinterpret_cast<uint32_t*>(&h);
    lo = *reinterpret_cast<uint32_t*>(&l);
}

// ---------------- prologue: split weights into chunked bf16 hi/lo images ----------------
__global__ void prep_weights(const float* __restrict__ W2, const float* __restrict__ W3) {
    int idx = blockIdx.x * blockDim.x + threadIdx.x;
    if (idx >= 98304) return;
    float w; size_t off; size_t losz;
    if (idx < 65536) {              // W2[n][k], n<256, k<256
        int n = idx >> 8, k = idx & 255;
        w = W2[idx];
        off = (size_t)(k >> 5) * 40960 + (size_t)n * BPITCHB + (size_t)(k & 31) * 2;
        losz = 20480;
    } else {                        // W3[n][k], n<128, k<256
        int i = idx - 65536;
        int n = i >> 8, k = i & 255;
        w = W3[i];
        off = IMG_W3_BASE + (size_t)(k >> 5) * 20480 + (size_t)n * BPITCHB + (size_t)(k & 31) * 2;
        losz = 10240;
    }
    __nv_bfloat16 h = __float2bfloat16(w);
    __nv_bfloat16 l = __float2bfloat16(w - __bfloat162float(h));
    *(__nv_bfloat16*)(g_wimg + off) = h;
    *(__nv_bfloat16*)(g_wimg + off + losz) = l;
}

// ---------------- main kernel ----------------
extern "C" __global__ void __launch_bounds__(THREADS, 1)
mdp_mma_kernel(const float* __restrict__ log_p,
               const float* __restrict__ log_y,
               const float* __restrict__ log_xb,
               const float* __restrict__ log_q,
               const float* __restrict__ W1, const float* __restrict__ b1,
               const float* __restrict__ b2, const float* __restrict__ b3,
               const float* __restrict__ W4, const float* __restrict__ b4,
               const float* __restrict__ log_beta,
               const float* __restrict__ log_delta,
               float* __restrict__ out)
{
    extern __shared__ unsigned char dynsm[];
    const uint32_t raw = smem_u32(dynsm);
    const uint32_t abase = (raw + 127u) & ~127u;
    unsigned char* sm = dynsm + (abase - raw);

    unsigned char* smAH = sm + OFF_AH;
    unsigned char* smAL = sm + OFF_AL;
    float* W1s = (float*)(sm + OFF_W1S);
    float* b1s = (float*)(sm + OFF_B1S);
    float* b2s = (float*)(sm + OFF_B2S);
    float* b3s = (float*)(sm + OFF_B3S);
    float* W4s = (float*)(sm + OFF_W4S);
    float* b4s = (float*)(sm + OFF_B4S);
    float* h3  = (float*)(sm + OFF_WB);    // reused after weight streaming completes

    const uint32_t uAH = abase + OFF_AH;
    const uint32_t uAL = abase + OFF_AL;
    const uint32_t uWB = abase + OFF_WB;
    const uint32_t mb  = abase + OFF_MB;

    const int tid  = threadIdx.x;
    const int wid  = tid >> 5;
    const int lane = tid & 31;
    const int row0 = blockIdx.x * ROWSPB;

    const float delta = 1.0f / (1.0f + __expf(-log_delta[0]));
    float beta = __expf(log_beta[0]);
    beta = fminf(fmaxf(beta, 0.5f), 20.0f);

    // kick off first two weight-chunk loads immediately
    if (tid == 0) {
        MBARRIER_INIT(mb + 0, 1);
        MBARRIER_INIT(mb + 8, 1);
        FENCE_PROXY_ASYNC();
        MBARRIER_EXPECT_TX(mb + 0, 40960);
        bulk_copy(uWB,         g_wimg + 0,     40960, mb + 0);
        MBARRIER_EXPECT_TX(mb + 8, 40960);
        bulk_copy(uWB + 40960, g_wimg + 40960, 40960, mb + 8);
    }

    // stage small params
    for (int i = tid; i < 2048; i += THREADS) {
        const int k = i >> 3, c = i & 7;
        W1s[i] = (c < 7) ? W1[k * 7 + c] : 0.0f;
    }
    if (tid < 256) { b1s[tid] = b1[tid]; b2s[tid] = b2[tid]; }
    if (tid < 128) b3s[tid] = b3[tid];
    if (tid < 384) W4s[tid] = W4[tid];
    if (tid < 3)   b4s[tid] = b4[tid];
    __syncthreads();

    // ---- layer 1 (fp32 exact) -> A hi/lo bf16 in smem ----
    {
        const int m  = tid >> 2;
        const int k0 = (tid & 3) * 64;
        const int r  = row0 + m;
        float x0 = log_p[r * 3 + 0], x1 = log_p[r * 3 + 1], x2 = log_p[r * 3 + 2];
        float x3 = log_y[r];
        float x4 = delta * log_xb[r * 3 + 0] + (1.0f - delta) * log_q[r * 3 + 0];
        float x5 = delta * log_xb[r * 3 + 1] + (1.0f - delta) * log_q[r * 3 + 1];
        float x6 = delta * log_xb[r * 3 + 2] + (1.0f - delta) * log_q[r * 3 + 2];
        unsigned char* rowH = smAH + (size_t)m * (APITCH * 2);
        unsigned char* rowL = smAL + (size_t)m * (APITCH * 2);
        #pragma unroll 8
        for (int j = 0; j < 64; j += 2) {
            const int k = k0 + j;
            const float4 w0 = *(const float4*)&W1s[k * 8];
            const float4 w1 = *(const float4*)&W1s[k * 8 + 4];
            const float4 u0 = *(const float4*)&W1s[(k + 1) * 8];
            const float4 u1 = *(const float4*)&W1s[(k + 1) * 8 + 4];
            const float2 bb = *(const float2*)&b1s[k];
            float v0 = bb.x, v1 = bb.y;
            v0 = fmaf(x0, w0.x, v0); v1 = fmaf(x0, u0.x, v1);
            v0 = fmaf(x1, w0.y, v0); v1 = fmaf(x1, u0.y, v1);
            v0 = fmaf(x2, w0.z, v0); v1 = fmaf(x2, u0.z, v1);
            v0 = fmaf(x3, w0.w, v0); v1 = fmaf(x3, u0.w, v1);
            v0 = fmaf(x4, w1.x, v0); v1 = fmaf(x4, u1.x, v1);
            v0 = fmaf(x5, w1.y, v0); v1 = fmaf(x5, u1.y, v1);
            v0 = fmaf(x6, w1.z, v0); v1 = fmaf(x6, u1.z, v1);
            v0 = silu_f(v0); v1 = silu_f(v1);
            uint32_t hi, lo;
            bsplit2(v0, v1, hi, lo);
            *(uint32_t*)(rowH + k * 2) = hi;
            *(uint32_t*)(rowL + k * 2) = lo;
        }
    }
    __syncthreads();

    // per-thread fragment coordinates
    const int mrow = (wid >> 1) * 16;
    const uint32_t arow  = (uint32_t)((lane & 7) + ((lane >> 3) & 1) * 8);
    const uint32_t akoff = (uint32_t)(((lane >> 4) & 1) * 16);     // bytes
    const uint32_t brow  = (uint32_t)((lane & 7) + ((lane >> 4) & 1) * 8);
    const uint32_t bkoff = (uint32_t)(((lane >> 3) & 1) * 16);     // bytes
    const uint32_t aBaseH = uAH + (uint32_t)(mrow + arow) * 528 + akoff;
    const uint32_t aBaseL = uAL + (uint32_t)(mrow + arow) * 528 + akoff;

    // ================= layer 2: C[128,256], warp tile 16x128 =================
    {
        const int nb2 = (wid & 1) * 128;
        float acc[64];
        #pragma unroll
        for (int i = 0; i < 64; i++) acc[i] = 0.0f;

        for (int ch = 0; ch < 8; ch++) {
            const int buf = ch & 1;
            MBARRIER_WAIT_PARITY(mb + 8 * buf, (ch >> 1) & 1);
            const uint32_t bb = uWB + (uint32_t)buf * 40960;
            #pragma unroll
            for (int s = 0; s < 2; s++) {
                const int kg = ch * 32 + s * 16;
                uint32_t ah[4], al[4];
                ldsm4(aBaseH + (uint32_t)kg * 2, ah);
                ldsm4(aBaseL + (uint32_t)kg * 2, al);
                const uint32_t bk = (uint32_t)s * 32 + bkoff;
                #pragma unroll
                for (int g = 0; g < 8; g++) {
                    const uint32_t baddr = bb + (uint32_t)(nb2 + g * 16 + brow) * BPITCHB + bk;
                    uint32_t bh[4], bl[4];
                    ldsm4(baddr, bh);
                    mma16816(&acc[g * 8 + 0], ah, bh[0], bh[1]);
                    mma16816(&acc[g * 8 + 4], ah, bh[2], bh[3]);
                    mma16816(&acc[g * 8 + 0], al, bh[0], bh[1]);
                    mma16816(&acc[g * 8 + 4], al, bh[2], bh[3]);
                    ldsm4(baddr + 20480u, bl);
                    mma16816(&acc[g * 8 + 0], ah, bl[0], bl[1]);
                    mma16816(&acc[g * 8 + 4], ah, bl[2], bl[3]);
                }
            }
            __syncthreads();
            if (tid == 0) {
                if (ch < 6) {
                    MBARRIER_EXPECT_TX(mb + 8 * buf, 40960);
                    bulk_copy(uWB + (uint32_t)buf * 40960,
                              g_wimg + (size_t)(ch + 2) * 40960, 40960, mb + 8 * buf);
                } else {
                    MBARRIER_EXPECT_TX(mb + 8 * buf, 20480);
                    bulk_copy(uWB + (uint32_t)buf * 40960,
                              g_wimg + IMG_W3_BASE + (size_t)(ch - 6) * 20480, 20480, mb + 8 * buf);
                }
            }
        }

        // epilogue: silu(acc + b2) -> A hi/lo
        const int erow = mrow + (lane >> 2);
        const int ecp  = 2 * (lane & 3);
        #pragma unroll
        for (int g = 0; g < 8; g++) {
            #pragma unroll
            for (int h = 0; h < 2; h++) {
                const int col = nb2 + g * 16 + h * 8 + ecp;
                const int idx = g * 8 + h * 4;
                const float2 bb2 = *(const float2*)&b2s[col];
                uint32_t hi, lo;
                float v0 = silu_f(acc[idx + 0] + bb2.x);
                float v1 = silu_f(acc[idx + 1] + bb2.y);
                bsplit2(v0, v1, hi, lo);
                *(uint32_t*)(smAH + (size_t)erow * 528 + col * 2) = hi;
                *(uint32_t*)(smAL + (size_t)erow * 528 + col * 2) = lo;
                float v2 = silu_f(acc[idx + 2] + bb2.x);
                float v3 = silu_f(acc[idx + 3] + bb2.y);
                bsplit2(v2, v3, hi, lo);
                *(uint32_t*)(smAH + (size_t)(erow + 8) * 528 + col * 2) = hi;
                *(uint32_t*)(smAL + (size_t)(erow + 8) * 528 + col * 2) = lo;
            }
        }
    }
    __syncthreads();

    // ================= layer 3: C[128,128], warp tile 16x64 =================
    {
        const int nb3 = (wid & 1) * 64;
        float acc3[32];
        #pragma unroll
        for (int i = 0; i < 32; i++) acc3[i] = 0.0f;

        for (int c = 0; c < 8; c++) {
            const int li = 8 + c;
            const int buf = li & 1;
            MBARRIER_WAIT_PARITY(mb + 8 * buf, (li >> 1) & 1);
            const uint32_t bb = uWB + (uint32_t)buf * 40960;
            #pragma unroll
            for (int s = 0; s < 2; s++) {
                const int kg = c * 32 + s * 16;
                uint32_t ah[4], al[4];
                ldsm4(aBaseH + (uint32_t)kg * 2, ah);
                ldsm4(aBaseL + (uint32_t)kg * 2, al);
                const uint32_t bk = (uint32_t)s * 32 + bkoff;
                #pragma unroll
                for (int g = 0; g < 4; g++) {
                    const uint32_t baddr = bb + (uint32_t)(nb3 + g * 16 + brow) * BPITCHB + bk;
                    uint32_t bh[4], bl[4];
                    ldsm4(baddr, bh);
                    mma16816(&acc3[g * 8 + 0], ah, bh[0], bh[1]);
                    mma16816(&acc3[g * 8 + 4], ah, bh[2], bh[3]);
                    mma16816(&acc3[g * 8 + 0], al, bh[0], bh[1]);
                    mma16816(&acc3[g * 8 + 4], al, bh[2], bh[3]);
                    ldsm4(baddr + 10240u, bl);
                    mma16816(&acc3[g * 8 + 0], ah, bl[0], bl[1]);
                    mma16816(&acc3[g * 8 + 4], ah, bl[2], bl[3]);
                }
            }
            __syncthreads();
            if (tid == 0 && c < 6) {
                MBARRIER_EXPECT_TX(mb + 8 * buf, 20480);
                bulk_copy(uWB + (uint32_t)buf * 40960,
                          g_wimg + IMG_W3_BASE + (size_t)(c + 2) * 20480, 20480, mb + 8 * buf);
            }
        }

        // epilogue: silu(acc3 + b3) -> h3 fp32 (reuses weight-buffer smem)
        const int erow = mrow + (lane >> 2);
        const int ecp  = 2 * (lane & 3);
        #pragma unroll
        for (int g = 0; g < 4; g++) {
            #pragma unroll
            for (int h = 0; h < 2; h++) {
                const int col = nb3 + g * 16 + h * 8 + ecp;
                const int idx = g * 8 + h * 4;
                const float2 bb3 = *(const float2*)&b3s[col];
                float2 v01, v23;
                v01.x = silu_f(acc3[idx + 0] + bb3.x);
                v01.y = silu_f(acc3[idx + 1] + bb3.y);
                v23.x = silu_f(acc3[idx + 2] + bb3.x);
                v23.y = silu_f(acc3[idx + 3] + bb3.y);
                *(float2*)&h3[erow * 132 + col]       = v01;
                *(float2*)&h3[(erow + 8) * 132 + col] = v23;
            }
        }
    }
    __syncthreads();

    // ================= layer 4 + softmax =================
    if (tid < ROWSPB) {
        const int m = tid;
        const float* hr = h3 + m * 132;
        float l0 = b4s[0], l1 = b4s[1], l2 = b4s[2];
        #pragma unroll 8
        for (int k = 0; k < 128; k += 4) {
            const float4 hv = *(const float4*)&hr[k];
            const float4 w0 = *(const float4*)&W4s[k];
            const float4 w1 = *(const float4*)&W4s[128 + k];
            const float4 w2 = *(const float4*)&W4s[256 + k];
            l0 = fmaf(hv.x, w0.x, l0); l0 = fmaf(hv.y, w0.y, l0);
            l0 = fmaf(hv.z, w0.z, l0); l0 = fmaf(hv.w, w0.w, l0);
            l1 = fmaf(hv.x, w1.x, l1); l1 = fmaf(hv.y, w1.y, l1);
            l1 = fmaf(hv.z, w1.z, l1); l1 = fmaf(hv.w, w1.w, l1);
            l2 = fmaf(hv.x, w2.x, l2); l2 = fmaf(hv.y, w2.y, l2);
            l2 = fmaf(hv.z, w2.z, l2); l2 = fmaf(hv.w, w2.w, l2);
        }
        l0 *= beta; l1 *= beta; l2 *= beta;
        const float mx = fmaxf(l0, fmaxf(l1, l2));
        const float e0 = __expf(l0 - mx);
        const float e1 = __expf(l1 - mx);
        const float e2 = __expf(l2 - mx);
        const float inv = __frcp_rn(e0 + e1 + e2);
        const int r = row0 + m;
        out[r * 3 + 0] = e0 * inv;
        out[r * 3 + 1] = e1 * inv;
        out[r * 3 + 2] = e2 * inv;
    }
}

extern "C" void kernel_launch(void* const* d_in, const int* in_sizes, int n_in,
                              void* d_out, int out_size)
{
    const float* log_p     = (const float*)d_in[0];
    const float* log_y     = (const float*)d_in[1];
    const float* log_xb    = (const float*)d_in[2];
    const float* log_q     = (const float*)d_in[3];
    const float* W1        = (const float*)d_in[4];
    const float* b1        = (const float*)d_in[5];
    const float* W2        = (const float*)d_in[6];
    const float* b2        = (const float*)d_in[7];
    const float* W3        = (const float*)d_in[8];
    const float* b3        = (const float*)d_in[9];
    const float* W4        = (const float*)d_in[10];
    const float* b4        = (const float*)d_in[11];
    const float* log_beta  = (const float*)d_in[12];
    const float* log_delta = (const float*)d_in[13];
    float* out = (float*)d_out;

    const int B = in_sizes[1];
    const int grid = B / ROWSPB;

    prep_weights<<<96, 1024>>>(W2, W3);

    cudaFuncSetAttribute(mdp_mma_kernel,
                         cudaFuncAttributeMaxDynamicSharedMemorySize, SMEM_BYTES);

    mdp_mma_kernel<<<grid, THREADS, SMEM_BYTES>>>(
        log_p, log_y, log_xb, log_q,
        W1, b1, b2, b3, W4, b4,
        log_beta, log_delta, out);
}

// round 5
// speedup vs baseline: 3.4301x; 1.5137x over previous
#include <cuda_runtime.h>
#include <cuda_bf16.h>
#include <cstdint>

#define THREADS 512
#define ROWSPB  128

// ---- smem byte offsets (from 128-aligned base) ----
#define OFF_AHI  0              // 128x256 bf16 packed blocks: 65536
#define OFF_ALO  65536
#define OFF_WB   131072         // 4 buffers x 16384
#define OFF_W1S  196608         // 8192
#define OFF_B1S  204800
#define OFF_B2S  205824
#define OFF_B3S  206848
#define OFF_W4S  207360
#define OFF_B4S  208896
#define OFF_PART 208912         // 128*12 floats = 6144
#define OFF_MB   215056         // full[4] cons[4] = 64
#define SMEM_BYTES (215120 + 256)

// weight image: W2 = 16 k16-chunks x 16384 (hi 8192 | lo 8192); W3 at 262144 = 16 x 8192 (hi 4096 | lo 4096)
#define IMG3 262144
__device__ __align__(16) unsigned char g_wimg[262144 + 131072];

// ---------------- helpers ----------------
__device__ __forceinline__ uint32_t smem_u32(const void* p) {
    uint32_t a;
    asm("{ .reg .u64 t; cvta.to.shared.u64 t, %1; cvt.u32.u64 %0, t; }" : "=r"(a) : "l"(p));
    return a;
}

#define MBARRIER_INIT(addr, cnt) \
    asm volatile("mbarrier.init.shared.b64 [%0], %1;" :: "r"((uint32_t)(addr)), "r"((uint32_t)(cnt)) : "memory")
#define MBARRIER_ARRIVE(addr) \
    asm volatile("mbarrier.arrive.shared.b64 _, [%0];" :: "r"((uint32_t)(addr)) : "memory")
#define MBARRIER_EXPECT_TX(addr, bytes) \
    asm volatile("mbarrier.arrive.expect_tx.shared.b64 _, [%0], %1;" :: "r"((uint32_t)(addr)), "r"((uint32_t)(bytes)) : "memory")
#define MBARRIER_WAIT_PARITY(addr, parity) do {                                   \
    uint32_t _mb = (uint32_t)(addr); uint32_t _p = (uint32_t)(parity);            \
    asm volatile(                                                                 \
        "{\n\t.reg .pred P;\n\t"                                                  \
        "WL_%=:\n\t"                                                              \
        "mbarrier.try_wait.parity.acquire.cta.shared::cta.b64 P, [%0], %1, 0x989680;\n\t" \
        "@P bra.uni WD_%=;\n\t"                                                   \
        "bra.uni WL_%=;\n\t"                                                      \
        "WD_%=:\n\t}"                                                             \
        :: "r"(_mb), "r"(_p) : "memory");                                         \
} while (0)
#define FENCE_PROXY_ASYNC() asm volatile("fence.proxy.async.shared::cta;" ::: "memory")

__device__ __forceinline__ void bulk_copy(uint32_t smem_dst, const void* gsrc,
                                          uint32_t bytes, uint32_t mbar) {
    uint64_t g = (uint64_t)__cvta_generic_to_global(gsrc);
    asm volatile(
        "cp.async.bulk.shared::cta.global.mbarrier::complete_tx::bytes [%0], [%1], %2, [%3];"
        :: "r"(smem_dst), "l"(g), "r"(bytes), "r"(mbar) : "memory");
}

__device__ __forceinline__ void ldsm4(uint32_t a, uint32_t* r) {
    asm volatile("ldmatrix.sync.aligned.m8n8.x4.shared.b16 {%0,%1,%2,%3}, [%4];"
        : "=r"(r[0]), "=r"(r[1]), "=r"(r[2]), "=r"(r[3]) : "r"(a));
}

__device__ __forceinline__ void mma16816(float* d, const uint32_t* a, uint32_t b0, uint32_t b1) {
    asm("mma.sync.aligned.m16n8k16.row.col.f32.bf16.bf16.f32 "
        "{%0,%1,%2,%3}, {%4,%5,%6,%7}, {%8,%9}, {%0,%1,%2,%3};"
        : "+f"(d[0]), "+f"(d[1]), "+f"(d[2]), "+f"(d[3])
        : "r"(a[0]), "r"(a[1]), "r"(a[2]), "r"(a[3]), "r"(b0), "r"(b1));
}

__device__ __forceinline__ float silu_f(float x) {
    return __fdividef(x, 1.0f + __expf(-x));
}

__device__ __forceinline__ void bsplit2(float a, float b, uint32_t& hi, uint32_t& lo) {
    __nv_bfloat162 h = __floats2bfloat162_rn(a, b);
    __nv_bfloat162 l = __floats2bfloat162_rn(a - __low2float(h), b - __high2float(h));
    hi = *reinterpret_cast<uint32_t*>(&h);
    lo = *reinterpret_cast<uint32_t*>(&l);
}

// packed-block byte offset for A: (m,k) in 128x256, blocks 16x16 = 4 contiguous 8x8 tiles
__device__ __forceinline__ uint32_t a_off(int m, int k) {
    return (uint32_t)((m >> 4) * 8192 + (k >> 4) * 512 +
           (((m & 8) >> 3) + ((k & 8) >> 3) * 2) * 128 + (m & 7) * 16 + (k & 7) * 2);
}

// ---------------- prologue: split + pack weights ----------------
__global__ void prep_weights(const float* __restrict__ W2, const float* __restrict__ W3) {
    int idx = blockIdx.x * blockDim.x + threadIdx.x;
    if (idx >= 98304) return;
    float w; size_t off; size_t lod;
    if (idx < 65536) {                   // W2[n][k]
        int n = idx >> 8, k = idx & 255;
        w = W2[idx];
        int u = ((n & 8) >> 3) * 2 + ((k & 8) >> 3);
        off = (size_t)(k >> 4) * 16384 + (size_t)(n >> 4) * 512 + u * 128 + (n & 7) * 16 + (k & 7) * 2;
        lod = 8192;
    } else {                             // W3[n][k], n<128
        int i = idx - 65536;
        int n = i >> 8, k = i & 255;
        w = W3[i];
        int u = ((n & 8) >> 3) * 2 + ((k & 8) >> 3);
        off = IMG3 + (size_t)(k >> 4) * 8192 + (size_t)(n >> 4) * 512 + u * 128 + (n & 7) * 16 + (k & 7) * 2;
        lod = 4096;
    }
    __nv_bfloat16 h = __float2bfloat16(w);
    __nv_bfloat16 l = __float2bfloat16(w - __bfloat162float(h));
    *(__nv_bfloat16*)(g_wimg + off) = h;
    *(__nv_bfloat16*)(g_wimg + off + lod) = l;
}

// ---------------- main kernel ----------------
extern "C" __global__ void __launch_bounds__(THREADS, 1)
mdp_mma_kernel(const float* __restrict__ log_p,
               const float* __restrict__ log_y,
               const float* __restrict__ log_xb,
               const float* __restrict__ log_q,
               const float* __restrict__ W1, const float* __restrict__ b1,
               const float* __restrict__ b2, const float* __restrict__ b3,
               const float* __restrict__ W4, const float* __restrict__ b4,
               const float* __restrict__ log_beta,
               const float* __restrict__ log_delta,
               float* __restrict__ out)
{
    extern __shared__ unsigned char dynsm[];
    const uint32_t raw = smem_u32(dynsm);
    const uint32_t abase = (raw + 127u) & ~127u;
    unsigned char* sm = dynsm + (abase - raw);

    float* W1s = (float*)(sm + OFF_W1S);
    float* b1s = (float*)(sm + OFF_B1S);
    float* b2s = (float*)(sm + OFF_B2S);
    float* b3s = (float*)(sm + OFF_B3S);
    float* W4s = (float*)(sm + OFF_W4S);
    float* b4s = (float*)(sm + OFF_B4S);
    float* part = (float*)(sm + OFF_PART);

    const uint32_t uAH = abase + OFF_AHI;
    const uint32_t uWB = abase + OFF_WB;
    const uint32_t mbF = abase + OFF_MB;        // full[i] at +8*i
    const uint32_t mbC = abase + OFF_MB + 32;   // cons[i] at +8*i

    const int tid  = threadIdx.x;
    const int wid  = tid >> 5;
    const int lane = tid & 31;
    const int row0 = blockIdx.x * ROWSPB;

    const float delta = 1.0f / (1.0f + __expf(-log_delta[0]));
    float beta = __expf(log_beta[0]);
    beta = fminf(fmaxf(beta, 0.5f), 20.0f);

    // init barriers + kick off first 4 chunk loads
    if (tid == 0) {
        #pragma unroll
        for (int i = 0; i < 4; i++) {
            MBARRIER_INIT(mbF + 8 * i, 1);
            MBARRIER_INIT(mbC + 8 * i, 16);
        }
        FENCE_PROXY_ASYNC();
        #pragma unroll
        for (int i = 0; i < 4; i++) {
            MBARRIER_EXPECT_TX(mbF + 8 * i, 16384);
            bulk_copy(uWB + i * 16384, g_wimg + (size_t)i * 16384, 16384, mbF + 8 * i);
        }
    }

    // stage small params
    for (int i = tid; i < 2048; i += THREADS) {
        const int k = i >> 3, c = i & 7;
        W1s[i] = (c < 7) ? W1[k * 7 + c] : 0.0f;
    }
    if (tid < 256) { b1s[tid] = b1[tid]; b2s[tid] = b2[tid]; }
    if (tid < 128) b3s[tid] = b3[tid];
    if (tid < 384) W4s[tid] = W4[tid];
    if (tid < 3)   b4s[tid] = b4[tid];
    __syncthreads();

    // ---- layer 1 (fp32 exact) -> packed A hi/lo ----
    {
        const int m  = tid & 127;
        const int k0 = (tid >> 7) * 64;
        const int r  = row0 + m;
        float x0 = log_p[r * 3 + 0], x1 = log_p[r * 3 + 1], x2 = log_p[r * 3 + 2];
        float x3 = log_y[r];
        float x4 = delta * log_xb[r * 3 + 0] + (1.0f - delta) * log_q[r * 3 + 0];
        float x5 = delta * log_xb[r * 3 + 1] + (1.0f - delta) * log_q[r * 3 + 1];
        float x6 = delta * log_xb[r * 3 + 2] + (1.0f - delta) * log_q[r * 3 + 2];
        #pragma unroll 8
        for (int j = 0; j < 64; j += 2) {
            const int k = k0 + j;
            const float4 w0 = *(const float4*)&W1s[k * 8];
            const float4 w1 = *(const float4*)&W1s[k * 8 + 4];
            const float4 u0 = *(const float4*)&W1s[(k + 1) * 8];
            const float4 u1 = *(const float4*)&W1s[(k + 1) * 8 + 4];
            const float2 bb = *(const float2*)&b1s[k];
            float v0 = bb.x, v1 = bb.y;
            v0 = fmaf(x0, w0.x, v0); v1 = fmaf(x0, u0.x, v1);
            v0 = fmaf(x1, w0.y, v0); v1 = fmaf(x1, u0.y, v1);
            v0 = fmaf(x2, w0.z, v0); v1 = fmaf(x2, u0.z, v1);
            v0 = fmaf(x3, w0.w, v0); v1 = fmaf(x3, u0.w, v1);
            v0 = fmaf(x4, w1.x, v0); v1 = fmaf(x4, u1.x, v1);
            v0 = fmaf(x5, w1.y, v0); v1 = fmaf(x5, u1.y, v1);
            v0 = fmaf(x6, w1.z, v0); v1 = fmaf(x6, u1.z, v1);
            v0 = silu_f(v0); v1 = silu_f(v1);
            uint32_t hi, lo;
            bsplit2(v0, v1, hi, lo);
            const uint32_t ao = a_off(m, k);
            *(uint32_t*)(sm + OFF_AHI + ao) = hi;
            *(uint32_t*)(sm + OFF_ALO + ao) = lo;
        }
    }
    __syncthreads();

    // warp tiling: 4m x 4n
    const int mw = wid & 3;
    const int nw = wid >> 2;
    const int mrow = mw * 32;
    const uint32_t aB0 = uAH + (uint32_t)(mw * 2) * 8192 + (uint32_t)lane * 16;
    const uint32_t aB1 = aB0 + 8192;

    // ================= layer 2: C[128,256], warp tile 32x64 =================
    float acc[64];
    #pragma unroll
    for (int i = 0; i < 64; i++) acc[i] = 0.0f;

    for (int ci = 0; ci < 16; ci++) {
        const int buf = ci & 3;
        const int par = (ci >> 2) & 1;
        MBARRIER_WAIT_PARITY(mbF + 8 * buf, par);

        const uint32_t koff = (uint32_t)ci * 512;
        uint32_t ah0[4], ah1[4], al0[4], al1[4];
        ldsm4(aB0 + koff, ah0);
        ldsm4(aB1 + koff, ah1);
        ldsm4(aB0 + 65536 + koff, al0);
        ldsm4(aB1 + 65536 + koff, al1);

        const uint32_t bBase = uWB + (uint32_t)buf * 16384 + (uint32_t)(nw * 4) * 512 + (uint32_t)lane * 16;
        uint32_t bh[16];
        #pragma unroll
        for (int g = 0; g < 4; g++) ldsm4(bBase + g * 512, bh + 4 * g);

        // pass 1: A_hi x B_hi
        #pragma unroll
        for (int g = 0; g < 4; g++) {
            mma16816(&acc[g * 16 + 0],  ah0, bh[4 * g + 0], bh[4 * g + 1]);
            mma16816(&acc[g * 16 + 4],  ah0, bh[4 * g + 2], bh[4 * g + 3]);
            mma16816(&acc[g * 16 + 8],  ah1, bh[4 * g + 0], bh[4 * g + 1]);
            mma16816(&acc[g * 16 + 12], ah1, bh[4 * g + 2], bh[4 * g + 3]);
        }
        // pass 2: A_lo x B_hi
        #pragma unroll
        for (int g = 0; g < 4; g++) {
            mma16816(&acc[g * 16 + 0],  al0, bh[4 * g + 0], bh[4 * g + 1]);
            mma16816(&acc[g * 16 + 4],  al0, bh[4 * g + 2], bh[4 * g + 3]);
            mma16816(&acc[g * 16 + 8],  al1, bh[4 * g + 0], bh[4 * g + 1]);
            mma16816(&acc[g * 16 + 12], al1, bh[4 * g + 2], bh[4 * g + 3]);
        }
        // pass 3: A_hi x B_lo
        uint32_t bl[16];
        #pragma unroll
        for (int g = 0; g < 4; g++) ldsm4(bBase + 8192 + g * 512, bl + 4 * g);
        #pragma unroll
        for (int g = 0; g < 4; g++) {
            mma16816(&acc[g * 16 + 0],  ah0, bl[4 * g + 0], bl[4 * g + 1]);
            mma16816(&acc[g * 16 + 4],  ah0, bl[4 * g + 2], bl[4 * g + 3]);
            mma16816(&acc[g * 16 + 8],  ah1, bl[4 * g + 0], bl[4 * g + 1]);
            mma16816(&acc[g * 16 + 12], ah1, bl[4 * g + 2], bl[4 * g + 3]);
        }

        if (lane == 0) MBARRIER_ARRIVE(mbC + 8 * buf);
        if (tid == 0 && ci + 4 < 32) {
            MBARRIER_WAIT_PARITY(mbC + 8 * buf, par);
            const int nx = ci + 4;
            const uint32_t sz = (nx < 16) ? 16384u : 8192u;
            const unsigned char* src = (nx < 16) ? (g_wimg + (size_t)nx * 16384)
                                                 : (g_wimg + IMG3 + (size_t)(nx - 16) * 8192);
            MBARRIER_EXPECT_TX(mbF + 8 * buf, sz);
            bulk_copy(uWB + (uint32_t)buf * 16384, src, sz, mbF + 8 * buf);
        }
    }
    __syncthreads();   // everyone done reading A before overwrite

    // epilogue: silu(acc + b2) -> packed A hi/lo
    {
        const int rbase = mrow + (lane >> 2);
        const int cbase = 2 * (lane & 3);
        #pragma unroll
        for (int g = 0; g < 4; g++) {
            #pragma unroll
            for (int m2 = 0; m2 < 2; m2++) {
                #pragma unroll
                for (int h = 0; h < 2; h++) {
                    const int idx = g * 16 + m2 * 8 + h * 4;
                    const int col = nw * 64 + g * 16 + h * 8 + cbase;
                    const float2 bb2 = *(const float2*)&b2s[col];
                    uint32_t hi, lo;
                    float v0 = silu_f(acc[idx + 0] + bb2.x);
                    float v1 = silu_f(acc[idx + 1] + bb2.y);
                    bsplit2(v0, v1, hi, lo);
                    uint32_t ao = a_off(rbase + m2 * 16, col);
                    *(uint32_t*)(sm + OFF_AHI + ao) = hi;
                    *(uint32_t*)(sm + OFF_ALO + ao) = lo;
                    float v2 = silu_f(acc[idx + 2] + bb2.x);
                    float v3 = silu_f(acc[idx + 3] + bb2.y);
                    bsplit2(v2, v3, hi, lo);
                    ao = a_off(rbase + m2 * 16 + 8, col);
                    *(uint32_t*)(sm + OFF_AHI + ao) = hi;
                    *(uint32_t*)(sm + OFF_ALO + ao) = lo;
                }
            }
        }
    }
    __syncthreads();

    // ================= layer 3: C[128,128], warp tile 32x32 =================
    float acc3[32];
    #pragma unroll
    for (int i = 0; i < 32; i++) acc3[i] = 0.0f;

    for (int ci = 16; ci < 32; ci++) {
        const int buf = ci & 3;
        const int par = (ci >> 2) & 1;
        MBARRIER_WAIT_PARITY(mbF + 8 * buf, par);

        const uint32_t koff = (uint32_t)(ci - 16) * 512;
        uint32_t ah0[4], ah1[4], al0[4], al1[4];
        ldsm4(aB0 + koff, ah0);
        ldsm4(aB1 + koff, ah1);
        ldsm4(aB0 + 65536 + koff, al0);
        ldsm4(aB1 + 65536 + koff, al1);

        const uint32_t bBase = uWB + (uint32_t)buf * 16384 + (uint32_t)(nw * 2) * 512 + (uint32_t)lane * 16;
        uint32_t bh[8], bl[8];
        #pragma unroll
        for (int g = 0; g < 2; g++) ldsm4(bBase + g * 512, bh + 4 * g);
        #pragma unroll
        for (int g = 0; g < 2; g++) {
            mma16816(&acc3[g * 16 + 0],  ah0, bh[4 * g + 0], bh[4 * g + 1]);
            mma16816(&acc3[g * 16 + 4],  ah0, bh[4 * g + 2], bh[4 * g + 3]);
            mma16816(&acc3[g * 16 + 8],  ah1, bh[4 * g + 0], bh[4 * g + 1]);
            mma16816(&acc3[g * 16 + 12], ah1, bh[4 * g + 2], bh[4 * g + 3]);
        }
        #pragma unroll
        for (int g = 0; g < 2; g++) {
            mma16816(&acc3[g * 16 + 0],  al0, bh[4 * g + 0], bh[4 * g + 1]);
            mma16816(&acc3[g * 16 + 4],  al0, bh[4 * g + 2], bh[4 * g + 3]);
            mma16816(&acc3[g * 16 + 8],  al1, bh[4 * g + 0], bh[4 * g + 1]);
            mma16816(&acc3[g * 16 + 12], al1, bh[4 * g + 2], bh[4 * g + 3]);
        }
        #pragma unroll
        for (int g = 0; g < 2; g++) ldsm4(bBase + 4096 + g * 512, bl + 4 * g);
        #pragma unroll
        for (int g = 0; g < 2; g++) {
            mma16816(&acc3[g * 16 + 0],  ah0, bl[4 * g + 0], bl[4 * g + 1]);
            mma16816(&acc3[g * 16 + 4],  ah0, bl[4 * g + 2], bl[4 * g + 3]);
            mma16816(&acc3[g * 16 + 8],  ah1, bl[4 * g + 0], bl[4 * g + 1]);
            mma16816(&acc3[g * 16 + 12], ah1, bl[4 * g + 2], bl[4 * g + 3]);
        }

        if (lane == 0) MBARRIER_ARRIVE(mbC + 8 * buf);
        if (tid == 0 && ci + 4 < 32) {
            MBARRIER_WAIT_PARITY(mbC + 8 * buf, par);
            const int nx = ci + 4;
            MBARRIER_EXPECT_TX(mbF + 8 * buf, 8192);
            bulk_copy(uWB + (uint32_t)buf * 16384,
                      g_wimg + IMG3 + (size_t)(nx - 16) * 8192, 8192, mbF + 8 * buf);
        }
    }

    // ---- layer 4 partials from registers: silu(acc3+b3) . W4 ----
    {
        float p[4][3];
        #pragma unroll
        for (int s = 0; s < 4; s++) { p[s][0] = 0.f; p[s][1] = 0.f; p[s][2] = 0.f; }
        const int cb = 2 * (lane & 3);
        #pragma unroll
        for (int g = 0; g < 2; g++) {
            #pragma unroll
            for (int m2 = 0; m2 < 2; m2++) {
                #pragma unroll
                for (int h = 0; h < 2; h++) {
                    const int idx = g * 16 + m2 * 8 + h * 4;
                    const int col = nw * 32 + g * 16 + h * 8 + cb;
                    const float2 bb3 = *(const float2*)&b3s[col];
                    #pragma unroll
                    for (int j = 0; j < 4; j++) {
                        const int c = col + (j & 1);
                        const float v = silu_f(acc3[idx + j] + ((j & 1) ? bb3.y : bb3.x));
                        const int slot = m2 * 2 + (j >> 1);
                        p[slot][0] = fmaf(v, W4s[c],       p[slot][0]);
                        p[slot][1] = fmaf(v, W4s[128 + c], p[slot][1]);
                        p[slot][2] = fmaf(v, W4s[256 + c], p[slot][2]);
                    }
                }
            }
        }
        // reduce over the 4 lanes sharing each row (lane&3)
        #pragma unroll
        for (int s = 0; s < 4; s++)
            #pragma unroll
            for (int g = 0; g < 3; g++) {
                p[s][g] += __shfl_xor_sync(0xffffffffu, p[s][g], 1);
                p[s][g] += __shfl_xor_sync(0xffffffffu, p[s][g], 2);
            }
        if ((lane & 3) == 0) {
            const int r = lane >> 2;
            #pragma unroll
            for (int s = 0; s < 4; s++) {
                const int row = mrow + (s >> 1) * 16 + (s & 1) * 8 + r;
                part[row * 12 + nw * 3 + 0] = p[s][0];
                part[row * 12 + nw * 3 + 1] = p[s][1];
                part[row * 12 + nw * 3 + 2] = p[s][2];
            }
        }
    }
    __syncthreads();

    // ---- softmax + store ----
    if (tid < ROWSPB) {
        const int m = tid;
        float l0 = b4s[0], l1 = b4s[1], l2 = b4s[2];
        #pragma unroll
        for (int c = 0; c < 4; c++) {
            l0 += part[m * 12 + c * 3 + 0];
            l1 += part[m * 12 + c * 3 + 1];
            l2 += part[m * 12 + c * 3 + 2];
        }
        l0 *= beta; l1 *= beta; l2 *= beta;
        const float mx = fmaxf(l0, fmaxf(l1, l2));
        const float e0 = __expf(l0 - mx);
        const float e1 = __expf(l1 - mx);
        const float e2 = __expf(l2 - mx);
        const float inv = __frcp_rn(e0 + e1 + e2);
        const int r = row0 + m;
        out[r * 3 + 0] = e0 * inv;
        out[r * 3 + 1] = e1 * inv;
        out[r * 3 + 2] = e2 * inv;
    }
}

extern "C" void kernel_launch(void* const* d_in, const int* in_sizes, int n_in,
                              void* d_out, int out_size)
{
    const float* log_p     = (const float*)d_in[0];
    const float* log_y     = (const float*)d_in[1];
    const float* log_xb    = (const float*)d_in[2];
    const float* log_q     = (const float*)d_in[3];
    const float* W1        = (const float*)d_in[4];
    const float* b1        = (const float*)d_in[5];
    const float* W2        = (const float*)d_in[6];
    const float* b2        = (const float*)d_in[7];
    const float* W3        = (const float*)d_in[8];
    const float* b3        = (const float*)d_in[9];
    const float* W4        = (const float*)d_in[10];
    const float* b4        = (const float*)d_in[11];
    const float* log_beta  = (const float*)d_in[12];
    const float* log_delta = (const float*)d_in[13];
    float* out = (float*)d_out;

    const int B = in_sizes[1];
    const int grid = B / ROWSPB;

    prep_weights<<<96, 1024>>>(W2, W3);

    cudaFuncSetAttribute(mdp_mma_kernel,
                         cudaFuncAttributeMaxDynamicSharedMemorySize, SMEM_BYTES);

    mdp_mma_kernel<<<grid, THREADS, SMEM_BYTES>>>(
        log_p, log_y, log_xb, log_q,
        W1, b1, b2, b3, W4, b4,
        log_beta, log_delta, out);
}